// round 1
// baseline (speedup 1.0000x reference)
#include <cuda_runtime.h>
#include <math.h>

#define Bb    2
#define Ls    4096
#define Dd    1024
#define Hh    16
#define Gg    2
#define WINs  256
#define HDd   64
#define KVd   128
#define Ee    8
#define HIDs  1024
#define NTOK  8192     // B*L
#define QROWS 2176     // only query/key rows < 2176 per batch are ever used

// ---------------- scratch (static __device__ globals; no allocs allowed) ----
__device__ float g_ln1[NTOK * Dd];
__device__ float g_qb [NTOK * Dd];
__device__ float g_kb [NTOK * KVd];
__device__ float g_vb [NTOK * KVd];
__device__ float g_ob [NTOK * Dd];
__device__ float g_ln2[NTOK * Dd];
__device__ int   g_cnt[Ee];
__device__ int   g_list[Ee][NTOK];
__device__ float g_wl  [Ee][NTOK];
__device__ float g_entsum;

// ---------------- init: zero per-replay counters ---------------------------
__global__ void init_kernel() {
    int t = threadIdx.x;
    if (t < Ee) g_cnt[t] = 0;
    if (t == 0) g_entsum = 0.f;
}

// ---------------- layernorm (one block per row, 256 thr, float4) -----------
__device__ __forceinline__ float block_reduce_sum(float v, float* sh) {
    int lane = threadIdx.x & 31, w = threadIdx.x >> 5;
    #pragma unroll
    for (int o = 16; o; o >>= 1) v += __shfl_xor_sync(0xffffffffu, v, o);
    if (lane == 0) sh[w] = v;
    __syncthreads();
    if (w == 0) {
        float r = (lane < 8) ? sh[lane] : 0.f;
        #pragma unroll
        for (int o = 4; o; o >>= 1) r += __shfl_xor_sync(0xffffffffu, r, o);
        if (lane == 0) sh[0] = r;
    }
    __syncthreads();
    float r = sh[0];
    __syncthreads();
    return r;
}

__global__ __launch_bounds__(256) void ln_kernel(
    const float* __restrict__ x, const float* __restrict__ g,
    const float* __restrict__ b, float* __restrict__ out)
{
    __shared__ float sh[8];
    size_t row = blockIdx.x;
    const float4* xr = (const float4*)(x + row * Dd);
    float4 v = xr[threadIdx.x];
    float mean = block_reduce_sum(v.x + v.y + v.z + v.w, sh) * (1.f / Dd);
    float d0 = v.x - mean, d1 = v.y - mean, d2 = v.z - mean, d3 = v.w - mean;
    float var = block_reduce_sum(d0*d0 + d1*d1 + d2*d2 + d3*d3, sh) * (1.f / Dd);
    float inv = rsqrtf(var + 1e-5f);
    float4 gv = ((const float4*)g)[threadIdx.x];
    float4 bv = ((const float4*)b)[threadIdx.x];
    float4 o;
    o.x = d0 * inv * gv.x + bv.x;
    o.y = d1 * inv * gv.y + bv.y;
    o.z = d2 * inv * gv.z + bv.z;
    o.w = d3 * inv * gv.w + bv.w;
    ((float4*)(out + row * Dd))[threadIdx.x] = o;
}

// ---------------- generic SGEMM: C = A(MxK) * B(KxN) + bias (+ res) --------
// BM=BN=128, BK=16, 256 threads, 8x8 micro-tile. Grid must cover exact tiles.
__global__ __launch_bounds__(256) void sgemm_bias(
    const float* __restrict__ A, const float* __restrict__ Bm,
    const float* __restrict__ bias, const float* __restrict__ res,
    float* __restrict__ C, int Nn, int Kk)
{
    __shared__ float As[16][128];
    __shared__ float Bs[16][128];
    int m0 = blockIdx.y * 128;
    int n0 = blockIdx.x * 128;
    int tid = threadIdx.x;
    int tx = tid & 15, ty = tid >> 4;
    float acc[8][8] = {};
    for (int k0 = 0; k0 < Kk; k0 += 16) {
        #pragma unroll
        for (int it = 0; it < 2; it++) {
            int p  = tid + it * 256;
            int ar = p >> 2, ac = (p & 3) * 4;
            float4 av = *(const float4*)&A[(size_t)(m0 + ar) * Kk + k0 + ac];
            As[ac + 0][ar] = av.x; As[ac + 1][ar] = av.y;
            As[ac + 2][ar] = av.z; As[ac + 3][ar] = av.w;
            int br = p >> 5, bc = (p & 31) * 4;
            *(float4*)&Bs[br][bc] =
                *(const float4*)&Bm[(size_t)(k0 + br) * Nn + n0 + bc];
        }
        __syncthreads();
        #pragma unroll
        for (int k = 0; k < 16; k++) {
            float a[8], bb[8];
            #pragma unroll
            for (int i = 0; i < 8; i++) a[i] = As[k][ty * 8 + i];
            #pragma unroll
            for (int j = 0; j < 8; j++) bb[j] = Bs[k][tx * 8 + j];
            #pragma unroll
            for (int i = 0; i < 8; i++)
                #pragma unroll
                for (int j = 0; j < 8; j++) acc[i][j] += a[i] * bb[j];
        }
        __syncthreads();
    }
    #pragma unroll
    for (int i = 0; i < 8; i++) {
        size_t m = m0 + ty * 8 + i;
        #pragma unroll
        for (int j4 = 0; j4 < 8; j4 += 4) {
            int n = n0 + tx * 8 + j4;
            float4 v;
            v.x = acc[i][j4 + 0] + bias[n + 0];
            v.y = acc[i][j4 + 1] + bias[n + 1];
            v.z = acc[i][j4 + 2] + bias[n + 2];
            v.w = acc[i][j4 + 3] + bias[n + 3];
            if (res) {
                float4 r = *(const float4*)&res[m * Nn + n];
                v.x += r.x; v.y += r.y; v.z += r.z; v.w += r.w;
            }
            *(float4*)&C[m * Nn + n] = v;
        }
    }
}

// ---------------- windowed GQA attention -----------------------------------
// Output row t = n*256 + w (t < 4096): query pos n*128+w, keys [n*128, n*128+256)
__global__ __launch_bounds__(256, 1) void attn_kernel(
    const float* __restrict__ Q, const float* __restrict__ K,
    const float* __restrict__ V, float* __restrict__ O)
{
    extern __shared__ float smem[];
    float* Ks = smem;
    float* Vs = smem + WINs * HDd;
    int n = blockIdx.x, h = blockIdx.y, b = blockIdx.z;
    int g = h & (Gg - 1);
    int kbase = n * (WINs / 2);
    const float* Kg = K + ((size_t)b * Ls + kbase) * KVd + g * HDd;
    const float* Vg = V + ((size_t)b * Ls + kbase) * KVd + g * HDd;
    for (int i = threadIdx.x; i < WINs * HDd / 4; i += 256) {
        int r = i >> 4, c = (i & 15) * 4;
        *(float4*)&Ks[r * HDd + c] = *(const float4*)&Kg[(size_t)r * KVd + c];
        *(float4*)&Vs[r * HDd + c] = *(const float4*)&Vg[(size_t)r * KVd + c];
    }
    __syncthreads();
    int w = threadIdx.x;
    const float* qr = Q + ((size_t)b * Ls + kbase + w) * Dd + h * HDd;
    float q[HDd], acc[HDd];
    #pragma unroll
    for (int i = 0; i < HDd; i++) { q[i] = qr[i] * 0.125f; acc[i] = 0.f; }
    float mrun = -1e30f, lrun = 0.f;
    for (int kc = 0; kc < WINs; kc += 8) {
        float s[8];
        #pragma unroll
        for (int j = 0; j < 8; j++) {
            const float* kr = &Ks[(kc + j) * HDd];
            float d = 0.f;
            #pragma unroll
            for (int i = 0; i < HDd; i++) d += q[i] * kr[i];
            s[j] = d;
        }
        float cm = s[0];
        #pragma unroll
        for (int j = 1; j < 8; j++) cm = fmaxf(cm, s[j]);
        float nm = fmaxf(mrun, cm);
        float scale = __expf(mrun - nm);
        lrun *= scale;
        #pragma unroll
        for (int i = 0; i < HDd; i++) acc[i] *= scale;
        #pragma unroll
        for (int j = 0; j < 8; j++) {
            float ev = __expf(s[j] - nm);
            lrun += ev;
            const float* vr = &Vs[(kc + j) * HDd];
            #pragma unroll
            for (int i = 0; i < HDd; i++) acc[i] += ev * vr[i];
        }
        mrun = nm;
    }
    float inv = 1.f / lrun;
    float* orow = O + ((size_t)b * Ls + n * WINs + w) * Dd + h * HDd;
    #pragma unroll
    for (int i = 0; i < HDd; i += 4) {
        float4 o4 = make_float4(acc[i] * inv, acc[i+1] * inv,
                                acc[i+2] * inv, acc[i+3] * inv);
        *(float4*)&orow[i] = o4;
    }
}

// ---------------- gating: warp per token ------------------------------------
__global__ __launch_bounds__(256) void gate_kernel(
    const float* __restrict__ X, const float* __restrict__ Wg,
    const float* __restrict__ bg)
{
    int tok  = (blockIdx.x * 256 + threadIdx.x) >> 5;
    int lane = threadIdx.x & 31;
    if (tok >= NTOK) return;
    const float* xr = X + (size_t)tok * Dd;
    float a[Ee];
    #pragma unroll
    for (int e = 0; e < Ee; e++) a[e] = 0.f;
    for (int d = lane; d < Dd; d += 32) {
        float xv = xr[d];
        const float4* wr = (const float4*)&Wg[d * Ee];
        float4 w0 = wr[0], w1 = wr[1];
        a[0] += xv * w0.x; a[1] += xv * w0.y; a[2] += xv * w0.z; a[3] += xv * w0.w;
        a[4] += xv * w1.x; a[5] += xv * w1.y; a[6] += xv * w1.z; a[7] += xv * w1.w;
    }
    #pragma unroll
    for (int e = 0; e < Ee; e++)
        #pragma unroll
        for (int o = 16; o; o >>= 1) a[e] += __shfl_xor_sync(0xffffffffu, a[e], o);
    if (lane == 0) {
        float mx = -1e30f;
        #pragma unroll
        for (int e = 0; e < Ee; e++) { a[e] += bg[e]; mx = fmaxf(mx, a[e]); }
        float p[Ee], se = 0.f;
        #pragma unroll
        for (int e = 0; e < Ee; e++) { p[e] = __expf(a[e] - mx); se += p[e]; }
        float inv = 1.f / se, ent = 0.f;
        #pragma unroll
        for (int e = 0; e < Ee; e++) { p[e] *= inv; ent -= p[e] * logf(p[e] + 1e-8f); }
        atomicAdd(&g_entsum, ent);
        int i0 = 0;
        #pragma unroll
        for (int e = 1; e < Ee; e++) if (p[e] > p[i0]) i0 = e;
        int i1 = -1;
        #pragma unroll
        for (int e = 0; e < Ee; e++) {
            if (e == i0) continue;
            if (i1 < 0 || p[e] > p[i1]) i1 = e;
        }
        int p0 = atomicAdd(&g_cnt[i0], 1);
        g_list[i0][p0] = tok; g_wl[i0][p0] = p[i0];
        int p1 = atomicAdd(&g_cnt[i1], 1);
        g_list[i1][p1] = tok; g_wl[i1][p1] = p[i1];
    }
}

// ---------------- grouped MoE GEMM: out[tok] += w * (x @ We[e] + be[e]) -----
__global__ __launch_bounds__(256) void moe_gemm(
    const float* __restrict__ X, const float* __restrict__ We,
    const float* __restrict__ be, float* __restrict__ out)
{
    int e = blockIdx.z;
    int cnt = g_cnt[e];
    int m0 = blockIdx.y * 128;
    if (m0 >= cnt) return;
    int n0 = blockIdx.x * 128;
    const float* Bm = We + (size_t)e * Dd * HIDs;
    __shared__ float As[16][128];
    __shared__ float Bs[16][128];
    __shared__ int ridx[128];
    int tid = threadIdx.x;
    if (tid < 128) {
        int m = m0 + tid;
        ridx[tid] = (m < cnt) ? g_list[e][m] : -1;
    }
    __syncthreads();
    int tx = tid & 15, ty = tid >> 4;
    float acc[8][8] = {};
    for (int k0 = 0; k0 < Dd; k0 += 16) {
        #pragma unroll
        for (int it = 0; it < 2; it++) {
            int p  = tid + it * 256;
            int ar = p >> 2, ac = (p & 3) * 4;
            int tk = ridx[ar];
            float4 av = make_float4(0.f, 0.f, 0.f, 0.f);
            if (tk >= 0) av = *(const float4*)&X[(size_t)tk * Dd + k0 + ac];
            As[ac + 0][ar] = av.x; As[ac + 1][ar] = av.y;
            As[ac + 2][ar] = av.z; As[ac + 3][ar] = av.w;
            int br = p >> 5, bc = (p & 31) * 4;
            *(float4*)&Bs[br][bc] =
                *(const float4*)&Bm[(size_t)(k0 + br) * HIDs + n0 + bc];
        }
        __syncthreads();
        #pragma unroll
        for (int k = 0; k < 16; k++) {
            float a[8], bb[8];
            #pragma unroll
            for (int i = 0; i < 8; i++) a[i] = As[k][ty * 8 + i];
            #pragma unroll
            for (int j = 0; j < 8; j++) bb[j] = Bs[k][tx * 8 + j];
            #pragma unroll
            for (int i = 0; i < 8; i++)
                #pragma unroll
                for (int j = 0; j < 8; j++) acc[i][j] += a[i] * bb[j];
        }
        __syncthreads();
    }
    #pragma unroll
    for (int i = 0; i < 8; i++) {
        int m = m0 + ty * 8 + i;
        if (m >= cnt) continue;
        int tk = ridx[ty * 8 + i];
        float w = g_wl[e][m];
        float* orow = out + (size_t)tk * HIDs + n0;
        #pragma unroll
        for (int j = 0; j < 8; j++) {
            int nn = tx * 8 + j;
            atomicAdd(&orow[nn], w * (acc[i][j] + be[e * HIDs + n0 + nn]));
        }
    }
}

// ---------------- aux scalar ------------------------------------------------
__global__ void fin_kernel(float* __restrict__ out) {
    float pen = 0.f;
    #pragma unroll
    for (int e = 0; e < Ee; e++) {
        float usage = (float)g_cnt[e] / (8192.f + 1e-8f);
        pen += fmaxf(usage - 0.4f, 0.f);
    }
    out[(size_t)NTOK * Dd] = 0.05f * (g_entsum / (float)NTOK) + pen;
}

// ---------------- launch ----------------------------------------------------
extern "C" void kernel_launch(void* const* d_in, const int* in_sizes, int n_in,
                              void* d_out, int out_size)
{
    (void)in_sizes; (void)n_in;
    const float* x    = (const float*)d_in[0];
    const float* Wq   = (const float*)d_in[1];
    const float* bq   = (const float*)d_in[2];
    const float* Wk   = (const float*)d_in[3];
    const float* bk   = (const float*)d_in[4];
    const float* Wv   = (const float*)d_in[5];
    const float* bv   = (const float*)d_in[6];
    const float* Wo   = (const float*)d_in[7];
    const float* bo   = (const float*)d_in[8];
    const float* ln1g = (const float*)d_in[9];
    const float* ln1b = (const float*)d_in[10];
    const float* ln2g = (const float*)d_in[11];
    const float* ln2b = (const float*)d_in[12];
    const float* Wg   = (const float*)d_in[13];
    const float* bg   = (const float*)d_in[14];
    const float* We   = (const float*)d_in[15];
    const float* be   = (const float*)d_in[16];
    float* out = (float*)d_out;

    float *p_ln1, *p_q, *p_k, *p_v, *p_o, *p_ln2;
    cudaGetSymbolAddress((void**)&p_ln1, g_ln1);
    cudaGetSymbolAddress((void**)&p_q,   g_qb);
    cudaGetSymbolAddress((void**)&p_k,   g_kb);
    cudaGetSymbolAddress((void**)&p_v,   g_vb);
    cudaGetSymbolAddress((void**)&p_o,   g_ob);
    cudaGetSymbolAddress((void**)&p_ln2, g_ln2);

    init_kernel<<<1, 32>>>();
    ln_kernel<<<NTOK, 256>>>(x, ln1g, ln1b, p_ln1);

    // QKV projections — only rows < 2176 per batch are ever consumed (17 tiles)
    for (int b = 0; b < Bb; b++) {
        const float* Ab = p_ln1 + (size_t)b * Ls * Dd;
        sgemm_bias<<<dim3(8, QROWS / 128), 256>>>(
            Ab, Wq, bq, nullptr, p_q + (size_t)b * Ls * Dd, Dd, Dd);
        sgemm_bias<<<dim3(1, QROWS / 128), 256>>>(
            Ab, Wk, bk, nullptr, p_k + (size_t)b * Ls * KVd, KVd, Dd);
        sgemm_bias<<<dim3(1, QROWS / 128), 256>>>(
            Ab, Wv, bv, nullptr, p_v + (size_t)b * Ls * KVd, KVd, Dd);
    }

    const int attn_smem = 2 * WINs * HDd * sizeof(float);  // 128 KB
    cudaFuncSetAttribute(attn_kernel,
                         cudaFuncAttributeMaxDynamicSharedMemorySize, attn_smem);
    attn_kernel<<<dim3(16, Hh, Bb), 256, attn_smem>>>(p_q, p_k, p_v, p_o);

    // h = x + O @ Wo + bo   (written straight into d_out)
    sgemm_bias<<<dim3(8, NTOK / 128), 256>>>(p_o, Wo, bo, x, out, Dd, Dd);

    ln_kernel<<<NTOK, 256>>>(out, ln2g, ln2b, p_ln2);
    gate_kernel<<<NTOK * 32 / 256, 256>>>(p_ln2, Wg, bg);
    moe_gemm<<<dim3(HIDs / 128, NTOK / 128, Ee), 256>>>(p_ln2, We, be, out);

    if (out_size > NTOK * Dd) fin_kernel<<<1, 1>>>(out);
}